// round 16
// baseline (speedup 1.0000x reference)
#include <cuda_runtime.h>
#include <cfloat>
#include <cstdint>

#define CH          151
#define N_EDGES     47
#define GROUP_ROWS  32                    // rows per block-group == lanes
#define GROUP_F     (GROUP_ROWS * CH)     // 4832 floats per array
#define GROUP_V4    (GROUP_F / 4)         // 1208 float4
#define NWARP       16
#define THREADS     (NWARP * 32)          // 512
#define NV_ITERS    3                     // ceil(1208/512)
// double buffer x (q, t)
#define SMEM_BYTES  (2 * 2 * GROUP_F * 4) // 77,312 B dynamic

// ---- topology-shared edge slots -------------------------------------------
// 47 edges partitioned into 16 warp-slots, each covering only 4 joints:
//   type 0 PATH : edges (J0,J1) (J1,J2) (J2,J3)
//   type 1 STAR : edges (J0,J1) (J0,J2) (J0,J3)
//   type 2 PATH2: edges (J0,J1) (J1,J2)            (2 edges)
// Edge direction is irrelevant: flipping signs of all diffs leaves d*d
// unchanged. Mask channels use the ORIGINAL edge index (c*47+e layout).
__constant__ int4 c_jnt[NWARP] = {   // joint channel offsets (joint*3)
    {  0,  3,  6,  9}, { 27, 30, 33, 36}, { 39, 42, 45, 48}, { 51, 54, 57, 60},
    { 63, 66, 69, 72}, { 75, 78, 81, 84}, { 90, 93, 96, 99}, {102,105,108,111},
    {114,117,120,123}, {126,129,132,135}, {138,141,144,147}, { 24, 27, 39, 51},
    { 24, 63, 75, 18}, { 87, 90,102,114}, { 87,126,138,  9}, {  3, 15, 18, 18}};
__constant__ int4 c_me[NWARP] = {    // original edge indices for masks
    { 0, 1, 2,0}, {12,13,14,0}, {15,16,17,0}, {18,19,20,0},
    {21,22,23,0}, {24,25,26,0}, {32,33,34,0}, {35,36,37,0},
    {38,39,40,0}, {41,42,43,0}, {44,45,46,0}, { 7, 8, 9,0},
    {10,11, 6,0}, {27,28,29,0}, {30,31, 3,0}, { 4, 5, 0,0}};
__constant__ int c_type[NWARP] = {0,0,0,0,0,0,0,0,0,0,0,1,1,1,1,2};

// original edge tables (tail fallback only)
__constant__ int c_par3[N_EDGES] = {
    0,3,6,9,3,15,18,24,24,24,24,24,27,30,33,39,42,45,51,54,57,63,66,69,
    75,78,81,87,87,87,87,87,90,93,96,102,105,108,114,117,120,126,129,132,138,141,144};
__constant__ int c_chi3[N_EDGES] = {
    3,6,9,87,15,18,24,27,39,51,63,75,30,33,36,42,45,48,54,57,60,66,69,72,
    78,81,84,90,102,114,126,138,93,96,99,105,108,111,117,120,123,129,132,135,141,144,147};

// persistent accumulators; statically zero, last block resets after use
__device__ double   g_acc[2] = {0.0, 0.0};
__device__ unsigned g_ticket = 0;

extern __shared__ float smem_dyn[];

// one edge: inputs are joint coordinates (parent, child) of q and t
__device__ __forceinline__ void edge_contrib(
    float qpx, float qpy, float qpz, float qcx, float qcy, float qcz,
    float tpx, float tpy, float tpz, float tcx, float tcy, float tcz,
    const float* __restrict__ trow, int me, float& vel_acc)
{
    float dp0 = qpx - qcx, dp1 = qpy - qcy, dp2 = qpz - qcz;
    float dt0 = tpx - tcx, dt1 = tpy - tcy, dt2 = tpz - tcz;

    float np = fmaf(dp0, dp0, fmaf(dp1, dp1, dp2 * dp2));
    float nt = fmaf(dt0, dt0, fmaf(dt1, dt1, dt2 * dt2));

    // n==0 -> dp==0 -> d==0 regardless of clamp; exact vs ref
    float ip = rsqrtf(fmaxf(np, FLT_MIN));
    float it = rsqrtf(fmaxf(nt, FLT_MIN));

    float d0 = dp0 * ip - dt0 * it;
    float d1 = dp1 * ip - dt1 * it;
    float d2 = dp2 * ip - dt2 * it;

    if (trow[me]      != 0.f) vel_acc = fmaf(d0, d0, vel_acc);
    if (trow[47 + me] != 0.f) vel_acc = fmaf(d1, d1, vel_acc);
    if (trow[94 + me] != 0.f) vel_acc = fmaf(d2, d2, vel_acc);
}

// tail fallback straight from gmem (unused for this shape, kept for generality)
__device__ __forceinline__ void process_row_gmem(const float* __restrict__ p,
                                                 const float* __restrict__ t,
                                                 float& l1_acc, float& vel_acc)
{
    float l1 = 0.f;
    float q[CH];
    #pragma unroll 8
    for (int i = 0; i < CH; i++) {
        float tv = t[i];
        float pv = p[i];
        q[i] = (tv != 0.f) ? pv : 0.f;
        l1 += (tv != 0.f) ? fabsf(pv - tv) : 0.f;
    }
    l1_acc += l1;

    for (int e = 0; e < N_EDGES; e++) {
        int a = c_par3[e], b = c_chi3[e];
        edge_contrib(q[a], q[a+1], q[a+2], q[b], q[b+1], q[b+2],
                     t[a], t[a+1], t[a+2], t[b], t[b+1], t[b+2],
                     t, e, vel_acc);
    }
}

__global__ void __launch_bounds__(THREADS, 2)
reg_loss_kernel(const float* __restrict__ preds,
                const float* __restrict__ targets,
                float* __restrict__ out,
                int groups, int rows)
{
    __shared__ float s_red[2][NWARP];
    __shared__ bool  s_last;

    const int lane = threadIdx.x & 31;
    const int wloc = threadIdx.x >> 5;
    const int tid  = threadIdx.x;

    const int kcnt = (blockIdx.x < (unsigned)groups)
                   ? ((groups - 1 - blockIdx.x) / gridDim.x + 1) : 0;

    float l1_acc = 0.f, vel_acc = 0.f;

    // this warp's edge slot (uniform within warp)
    const int4 J  = c_jnt[wloc];
    const int4 ME = c_me[wloc];
    const int  ty = c_type[wloc];

    // register prefetch buffers for one group (this thread's slice)
    float4 pbuf[NV_ITERS], tbuf[NV_ITERS];

    auto load_group = [&](long g) {
        const float4* gp = (const float4*)(preds   + (size_t)g * GROUP_F);
        const float4* gt = (const float4*)(targets + (size_t)g * GROUP_F);
        #pragma unroll
        for (int i = 0; i < NV_ITERS; i++) {
            int idx = tid + i * THREADS;
            if (idx < GROUP_V4) {
                pbuf[i] = gp[idx];
                tbuf[i] = gt[idx];
            }
        }
    };

    if (kcnt > 0) load_group(blockIdx.x);

    for (int k = 0; k < kcnt; k++) {
        float* sQ = smem_dyn + (size_t)(k & 1) * (2 * GROUP_F);
        float* sT = sQ + GROUP_F;

        // ---- stage: fused L1 (exact fp32) + mask, STS q (masked p) + raw t ----
        // Writes buffer k&1; laggards still read buffer (k-1)&1 — disjoint.
        #pragma unroll
        for (int i = 0; i < NV_ITERS; i++) {
            int idx = tid + i * THREADS;
            if (idx < GROUP_V4) {
                float4 tv = tbuf[i];
                float4 pv = pbuf[i];
                float4 qv;
                qv.x = (tv.x != 0.f) ? pv.x : 0.f;
                qv.y = (tv.y != 0.f) ? pv.y : 0.f;
                qv.z = (tv.z != 0.f) ? pv.z : 0.f;
                qv.w = (tv.w != 0.f) ? pv.w : 0.f;
                l1_acc += ((tv.x != 0.f) ? fabsf(pv.x - tv.x) : 0.f)
                        + ((tv.y != 0.f) ? fabsf(pv.y - tv.y) : 0.f)
                        + ((tv.z != 0.f) ? fabsf(pv.z - tv.z) : 0.f)
                        + ((tv.w != 0.f) ? fabsf(pv.w - tv.w) : 0.f);
                ((float4*)sQ)[idx] = qv;
                ((float4*)sT)[idx] = tv;
            }
        }

        // issue next group's LDGs now; they complete under pass 2
        if (k + 1 < kcnt)
            load_group(blockIdx.x + (long)(k + 1) * gridDim.x);

        // ONE sync per group (see R14 proof: double buffer makes the
        // trailing sync unnecessary; stage(k+2) is gated by sync(k+1)).
        __syncthreads();

        // ---- pass 2: warp = edge-slot, lane = row (stride 151 -> no conflicts)
        {
            const float* qrow = sQ + lane * CH;
            const float* trow = sT + lane * CH;

            // load this slot's 4 joints once (24 LDS instead of 45)
            float q0x = qrow[J.x], q0y = qrow[J.x+1], q0z = qrow[J.x+2];
            float q1x = qrow[J.y], q1y = qrow[J.y+1], q1z = qrow[J.y+2];
            float q2x = qrow[J.z], q2y = qrow[J.z+1], q2z = qrow[J.z+2];
            float q3x = qrow[J.w], q3y = qrow[J.w+1], q3z = qrow[J.w+2];
            float t0x = trow[J.x], t0y = trow[J.x+1], t0z = trow[J.x+2];
            float t1x = trow[J.y], t1y = trow[J.y+1], t1z = trow[J.y+2];
            float t2x = trow[J.z], t2y = trow[J.z+1], t2z = trow[J.z+2];
            float t3x = trow[J.w], t3y = trow[J.w+1], t3z = trow[J.w+2];

            if (ty == 0) {            // PATH: (J0,J1) (J1,J2) (J2,J3)
                edge_contrib(q0x,q0y,q0z, q1x,q1y,q1z,
                             t0x,t0y,t0z, t1x,t1y,t1z, trow, ME.x, vel_acc);
                edge_contrib(q1x,q1y,q1z, q2x,q2y,q2z,
                             t1x,t1y,t1z, t2x,t2y,t2z, trow, ME.y, vel_acc);
                edge_contrib(q2x,q2y,q2z, q3x,q3y,q3z,
                             t2x,t2y,t2z, t3x,t3y,t3z, trow, ME.z, vel_acc);
            } else if (ty == 1) {     // STAR: (J0,J1) (J0,J2) (J0,J3)
                edge_contrib(q0x,q0y,q0z, q1x,q1y,q1z,
                             t0x,t0y,t0z, t1x,t1y,t1z, trow, ME.x, vel_acc);
                edge_contrib(q0x,q0y,q0z, q2x,q2y,q2z,
                             t0x,t0y,t0z, t2x,t2y,t2z, trow, ME.y, vel_acc);
                edge_contrib(q0x,q0y,q0z, q3x,q3y,q3z,
                             t0x,t0y,t0z, t3x,t3y,t3z, trow, ME.z, vel_acc);
            } else {                  // PATH2: (J0,J1) (J1,J2)
                edge_contrib(q0x,q0y,q0z, q1x,q1y,q1z,
                             t0x,t0y,t0z, t1x,t1y,t1z, trow, ME.x, vel_acc);
                edge_contrib(q1x,q1y,q1z, q2x,q2y,q2z,
                             t1x,t1y,t1z, t2x,t2y,t2z, trow, ME.y, vel_acc);
            }
        }
        // NO trailing sync: next iteration's stage writes the other buffer.
    }

    // tail rows (rows % 32) straight from gmem (empty for this dataset)
    if (blockIdx.x == 0 && wloc == 0) {
        for (int row = groups * GROUP_ROWS + lane; row < rows; row += 32) {
            process_row_gmem(preds + (size_t)row * CH,
                             targets + (size_t)row * CH, l1_acc, vel_acc);
        }
    }

    // ---- warp reduce ----
    #pragma unroll
    for (int o = 16; o > 0; o >>= 1) {
        l1_acc  += __shfl_down_sync(0xFFFFFFFFu, l1_acc,  o);
        vel_acc += __shfl_down_sync(0xFFFFFFFFu, vel_acc, o);
    }
    if (lane == 0) { s_red[0][wloc] = l1_acc; s_red[1][wloc] = vel_acc; }
    __syncthreads();

    // ---- block reduce + global accumulate + last-block finalize ----
    if (threadIdx.x == 0) {
        float a = 0.f, v = 0.f;
        #pragma unroll
        for (int i = 0; i < NWARP; i++) { a += s_red[0][i]; v += s_red[1][i]; }
        atomicAdd(&g_acc[0], (double)a);
        atomicAdd(&g_acc[1], (double)v);
        __threadfence();
        unsigned tk = atomicAdd(&g_ticket, 1u);
        s_last = (tk == gridDim.x - 1);
    }
    __syncthreads();

    if (s_last && threadIdx.x == 0) {
        double l1  = g_acc[0] / ((double)rows * (double)CH);
        double vel = g_acc[1] / ((double)rows * (double)(N_EDGES * 3));
        out[0] = (float)(l1 + 0.1 * vel);
        // reset persistent state so every graph replay starts identically
        g_acc[0] = 0.0;
        g_acc[1] = 0.0;
        __threadfence();
        atomicExch(&g_ticket, 0u);
    }
}

extern "C" void kernel_launch(void* const* d_in, const int* in_sizes, int n_in,
                              void* d_out, int out_size)
{
    const float* preds   = (const float*)d_in[0];
    const float* targets = (const float*)d_in[1];
    float* out = (float*)d_out;

    int n      = in_sizes[0];
    int rows   = n / CH;               // B*T = 131072
    int groups = rows / GROUP_ROWS;    // 4096

    cudaFuncSetAttribute(reg_loss_kernel,
                         cudaFuncAttributeMaxDynamicSharedMemorySize, SMEM_BYTES);

    // ONE launch: 296 blocks (2/SM, 77.3KB smem each), 16 warps per block
    reg_loss_kernel<<<296, THREADS, SMEM_BYTES>>>(preds, targets, out,
                                                  groups, rows);
}